// round 6
// baseline (speedup 1.0000x reference)
#include <cuda_runtime.h>
#include <cuda_fp16.h>
#include <math.h>
#include <cstdint>
#include <cstddef>

#define BSZ   2
#define T     2048
#define DM    2048
#define NH    16
#define DH    128
#define FF    8192
#define MTOK  (BSZ*T)
#define LNEPS 1e-5f
#define LOG2E 1.4426950408889634f

// ---------------- scratch ----------------------------------------------------
__device__ __align__(128) __half g_ln  [(size_t)MTOK*DM];
__device__ __align__(128) __half g_q   [(size_t)MTOK*DM];
__device__ __align__(128) __half g_k   [(size_t)MTOK*DM];
__device__ __align__(128) __half g_vt  [(size_t)DM*MTOK];   // V^T [DM][MTOK]
__device__ __align__(128) __half g_att [(size_t)MTOK*DM];
__device__ __align__(128) float  g_x1  [(size_t)MTOK*DM];
__device__ __align__(128) float  g_gate[(size_t)MTOK*FF];
__device__ __align__(128) __half g_hid [(size_t)MTOK*FF];
__device__ __align__(128) __half g_wqh [(size_t)DM*DM];
__device__ __align__(128) __half g_wkh [(size_t)DM*DM];
__device__ __align__(128) __half g_wvh [(size_t)DM*DM];
__device__ __align__(128) __half g_woh [(size_t)DM*DM];
__device__ __align__(128) __half g_wgh [(size_t)FF*DM];
__device__ __align__(128) __half g_wuh [(size_t)FF*DM];
__device__ __align__(128) __half g_wdh [(size_t)DM*FF];

// ---------------- helpers ----------------------------------------------------
__device__ __forceinline__ void cpasync16(uint32_t dst, const void* src) {
    asm volatile("cp.async.cg.shared.global [%0], [%1], 16;\n"
                 :: "r"(dst), "l"(__cvta_generic_to_global(src)) : "memory");
}

__device__ __forceinline__ void ldsm4(uint32_t* r, uint32_t addr) {
    asm volatile("ldmatrix.sync.aligned.m8n8.x4.shared.b16 {%0,%1,%2,%3}, [%4];"
                 : "=r"(r[0]), "=r"(r[1]), "=r"(r[2]), "=r"(r[3]) : "r"(addr));
}

__device__ __forceinline__ void mma16(float* d, const uint32_t* a, const uint32_t* b) {
    asm volatile(
        "mma.sync.aligned.m16n8k16.row.col.f32.f16.f16.f32 "
        "{%0,%1,%2,%3}, {%4,%5,%6,%7}, {%8,%9}, {%0,%1,%2,%3};"
        : "+f"(d[0]), "+f"(d[1]), "+f"(d[2]), "+f"(d[3])
        : "r"(a[0]), "r"(a[1]), "r"(a[2]), "r"(a[3]), "r"(b[0]), "r"(b[1]));
}

// ---------------- fp32 -> fp16 convert (8 elems / thread / iter) --------------
__global__ __launch_bounds__(256) void cvt_kernel(const float* __restrict__ in,
                                                  __half* __restrict__ o, int n) {
    int n8 = n >> 3;
    for (int i = blockIdx.x * 256 + threadIdx.x; i < n8; i += gridDim.x * 256) {
        float4 a = reinterpret_cast<const float4*>(in)[2 * i];
        float4 b = reinterpret_cast<const float4*>(in)[2 * i + 1];
        __half2 h0 = __floats2half2_rn(a.x, a.y);
        __half2 h1 = __floats2half2_rn(a.z, a.w);
        __half2 h2 = __floats2half2_rn(b.x, b.y);
        __half2 h3 = __floats2half2_rn(b.z, b.w);
        uint4 u;
        u.x = *reinterpret_cast<uint32_t*>(&h0);
        u.y = *reinterpret_cast<uint32_t*>(&h1);
        u.z = *reinterpret_cast<uint32_t*>(&h2);
        u.w = *reinterpret_cast<uint32_t*>(&h3);
        reinterpret_cast<uint4*>(o)[i] = u;
    }
}

// ---------------- LayerNorm (fp16 output) -------------------------------------
__global__ __launch_bounds__(256) void ln_kernel(
    const float* __restrict__ x, const float* __restrict__ w,
    const float* __restrict__ b, __half* __restrict__ y)
{
    int row = blockIdx.x;
    const float* xr = x + (size_t)row * DM;
    float v[8];
    float s = 0.f, ss = 0.f;
#pragma unroll
    for (int i = 0; i < 8; i++) {
        float t = xr[threadIdx.x + 256 * i];
        v[i] = t; s += t; ss += t * t;
    }
    __shared__ float r1[256], r2[256];
    r1[threadIdx.x] = s; r2[threadIdx.x] = ss;
    __syncthreads();
    for (int off = 128; off > 0; off >>= 1) {
        if (threadIdx.x < off) {
            r1[threadIdx.x] += r1[threadIdx.x + off];
            r2[threadIdx.x] += r2[threadIdx.x + off];
        }
        __syncthreads();
    }
    float mu  = r1[0] * (1.f / DM);
    float var = r2[0] * (1.f / DM) - mu * mu;
    float rstd = rsqrtf(var + LNEPS);
    __half* yr = y + (size_t)row * DM;
#pragma unroll
    for (int i = 0; i < 8; i++) {
        int c = threadIdx.x + 256 * i;
        yr[c] = __float2half((v[i] - mu) * rstd * w[c] + b[c]);
    }
}

// ---------------- fused flash attention ----------------------------------------
// q: [MTOK][DM] fp16, logits pre-scaled by log2e/sqrt(DH) (folded into Q proj)
// k: [MTOK][DM] fp16; vt: [DM][MTOK] fp16; out att: [MTOK][DM] fp16
// CTA: 128 q-rows of one (b,h). 8 warps, 16 q-rows each. KV tiles of 128 keys.
#define FA_SMEM (32768 + 2 * 65536)
__global__ __launch_bounds__(256, 1) void fattn_kernel(
    const __half* __restrict__ q, const __half* __restrict__ k,
    const __half* __restrict__ vt, __half* __restrict__ att)
{
    extern __shared__ char smem[];
    uint32_t sb = (uint32_t)__cvta_generic_to_shared(smem);
    int tid = threadIdx.x, wid = tid >> 5, l = tid & 31;

    int z = blockIdx.y;
    int b = z / NH, h = z % NH;
    int q0 = blockIdx.x * 128;
    const __half* Qp = q  + ((size_t)(b * T + q0)) * DM + h * DH;
    const __half* Kp = k  + ((size_t)(b * T)) * DM + h * DH;
    const __half* Vp = vt + ((size_t)(h * DH)) * MTOK + (size_t)b * T;
    __half* Op = att + ((size_t)(b * T + q0)) * DM + h * DH;

    // ---- Q tile: 128 rows x 128 halves = two [128][64] chunks at sb+0, sb+16K
#pragma unroll
    for (int i = 0; i < 8; i++) {
        int s = tid + i * 256;
        int r = s >> 4, u = s & 15;
        int ch = u >> 3, c16 = u & 7;
        uint32_t off = (uint32_t)(ch * 16384 + r * 128 + ((c16 * 16) ^ ((r & 7) << 4)));
        cpasync16(sb + off, Qp + (size_t)r * DM + u * 8);
    }
    asm volatile("cp.async.commit_group;" ::: "memory");

    auto load_kv = [&](int buf, int kt) {
        uint32_t kb_ = sb + 32768u + (uint32_t)buf * 65536u;
        uint32_t vb_ = kb_ + 32768u;
#pragma unroll
        for (int i = 0; i < 8; i++) {
            int s = tid + i * 256;
            int r = s >> 4, u = s & 15;
            int ch = u >> 3, c16 = u & 7;
            uint32_t off = (uint32_t)(ch * 16384 + r * 128 + ((c16 * 16) ^ ((r & 7) << 4)));
            cpasync16(kb_ + off, Kp + (size_t)(kt * 128 + r) * DM + u * 8);
        }
#pragma unroll
        for (int i = 0; i < 8; i++) {
            int s = tid + i * 256;
            int r = s >> 4, u = s & 15;
            int ch = u >> 3, c16 = u & 7;
            uint32_t off = (uint32_t)(ch * 16384 + r * 128 + ((c16 * 16) ^ ((r & 7) << 4)));
            cpasync16(vb_ + off, Vp + (size_t)r * MTOK + kt * 128 + u * 8);
        }
        asm volatile("cp.async.commit_group;" ::: "memory");
    };
    load_kv(0, 0);

    asm volatile("cp.async.wait_group 1;" ::: "memory");   // Q ready
    __syncthreads();

    uint32_t xm   = (uint32_t)((l & 7) << 4);
    uint32_t cselA = (uint32_t)(((l >> 4) & 1) << 4);
    uint32_t cselB = (uint32_t)(((l >> 3) & 1) << 4);
    int brlo = (l & 7) + (((l >> 4) & 1) << 3);

    uint32_t qf[8][4];
    {
        int arow = wid * 16 + (l & 15);
        uint32_t base = sb + (uint32_t)(arow * 128);
#pragma unroll
        for (int kb = 0; kb < 8; kb++) {
            int ch = kb >> 2, kk = kb & 3;
            ldsm4(qf[kb], base + (uint32_t)(ch * 16384) + (((uint32_t)(kk * 32) + cselA) ^ xm));
        }
    }

    float O[16][4];
#pragma unroll
    for (int i = 0; i < 16; i++)
#pragma unroll
        for (int j = 0; j < 4; j++) O[i][j] = 0.f;
    float m0 = -1e30f, m1 = -1e30f, l0 = 0.f, l1 = 0.f;

    const int NIT = T / 128;
    for (int it = 0; it < NIT; it++) {
        int cur = it & 1;
        if (it + 1 < NIT) {
            load_kv(cur ^ 1, it + 1);
            asm volatile("cp.async.wait_group 1;" ::: "memory");
        } else {
            asm volatile("cp.async.wait_group 0;" ::: "memory");
        }
        __syncthreads();

        uint32_t kbase = sb + 32768u + (uint32_t)cur * 65536u;
        uint32_t vbase = kbase + 32768u;

        // S = Q K^T  (logits already x log2e/sqrt(dh))
        float S[16][4];
#pragma unroll
        for (int i = 0; i < 16; i++)
#pragma unroll
            for (int j = 0; j < 4; j++) S[i][j] = 0.f;
#pragma unroll
        for (int kb = 0; kb < 8; kb++) {
            int ch = kb >> 2, kk = kb & 3;
            uint32_t kcol = kbase + (uint32_t)(ch * 16384) + (((uint32_t)(kk * 32) + cselB) ^ xm);
#pragma unroll
            for (int ng = 0; ng < 8; ng++) {
                uint32_t bf[4];
                ldsm4(bf, kcol + (uint32_t)((ng * 16 + brlo) * 128));
                mma16(S[2 * ng],     qf[kb], &bf[0]);
                mma16(S[2 * ng + 1], qf[kb], &bf[2]);
            }
        }

        // online softmax (base-2 domain)
        float mx0 = -1e30f, mx1 = -1e30f;
#pragma unroll
        for (int nt = 0; nt < 16; nt++) {
            mx0 = fmaxf(mx0, fmaxf(S[nt][0], S[nt][1]));
            mx1 = fmaxf(mx1, fmaxf(S[nt][2], S[nt][3]));
        }
        mx0 = fmaxf(mx0, __shfl_xor_sync(0xffffffffu, mx0, 1));
        mx0 = fmaxf(mx0, __shfl_xor_sync(0xffffffffu, mx0, 2));
        mx1 = fmaxf(mx1, __shfl_xor_sync(0xffffffffu, mx1, 1));
        mx1 = fmaxf(mx1, __shfl_xor_sync(0xffffffffu, mx1, 2));
        float mn0 = fmaxf(m0, mx0), mn1 = fmaxf(m1, mx1);
        float sc0 = exp2f(m0 - mn0), sc1 = exp2f(m1 - mn1);
        m0 = mn0; m1 = mn1;
        l0 *= sc0; l1 *= sc1;
#pragma unroll
        for (int nt = 0; nt < 16; nt++) {
            O[nt][0] *= sc0; O[nt][1] *= sc0;
            O[nt][2] *= sc1; O[nt][3] *= sc1;
        }
#pragma unroll
        for (int nt = 0; nt < 16; nt++) {
            S[nt][0] = exp2f(S[nt][0] - mn0);
            S[nt][1] = exp2f(S[nt][1] - mn0);
            S[nt][2] = exp2f(S[nt][2] - mn1);
            S[nt][3] = exp2f(S[nt][3] - mn1);
            l0 += S[nt][0] + S[nt][1];
            l1 += S[nt][2] + S[nt][3];
        }

        // O += P V   (P as in-register fp16 A-frags)
#pragma unroll
        for (int kb = 0; kb < 8; kb++) {
            uint32_t pa[4];
            __half2 h0 = __floats2half2_rn(S[2 * kb][0],     S[2 * kb][1]);
            __half2 h1 = __floats2half2_rn(S[2 * kb][2],     S[2 * kb][3]);
            __half2 h2 = __floats2half2_rn(S[2 * kb + 1][0], S[2 * kb + 1][1]);
            __half2 h3 = __floats2half2_rn(S[2 * kb + 1][2], S[2 * kb + 1][3]);
            pa[0] = *reinterpret_cast<uint32_t*>(&h0);
            pa[1] = *reinterpret_cast<uint32_t*>(&h1);
            pa[2] = *reinterpret_cast<uint32_t*>(&h2);
            pa[3] = *reinterpret_cast<uint32_t*>(&h3);
            int ch = kb >> 2, kk = kb & 3;
            uint32_t vcol = vbase + (uint32_t)(ch * 16384) + (((uint32_t)(kk * 32) + cselB) ^ xm);
#pragma unroll
            for (int ng = 0; ng < 8; ng++) {
                uint32_t bf[4];
                ldsm4(bf, vcol + (uint32_t)((ng * 16 + brlo) * 128));
                mma16(O[2 * ng],     pa, &bf[0]);
                mma16(O[2 * ng + 1], pa, &bf[2]);
            }
        }
        __syncthreads();
    }

    l0 += __shfl_xor_sync(0xffffffffu, l0, 1);
    l0 += __shfl_xor_sync(0xffffffffu, l0, 2);
    l1 += __shfl_xor_sync(0xffffffffu, l1, 1);
    l1 += __shfl_xor_sync(0xffffffffu, l1, 2);
    float inv0 = 1.f / l0, inv1 = 1.f / l1;

    int g = l >> 2, q4 = l & 3;
#pragma unroll
    for (int nt = 0; nt < 16; nt++) {
        int c = nt * 8 + q4 * 2;
        *reinterpret_cast<__half2*>(&Op[(size_t)(wid * 16 + g) * DM + c]) =
            __floats2half2_rn(O[nt][0] * inv0, O[nt][1] * inv0);
        *reinterpret_cast<__half2*>(&Op[(size_t)(wid * 16 + g + 8) * DM + c]) =
            __floats2half2_rn(O[nt][2] * inv1, O[nt][3] * inv1);
    }
}

// ---------------- fp16 mma.sync NT GEMM ---------------------------------------
// EPI 0: float C = alpha*acc       EPI 1: float C = Res + alpha*acc
// EPI 2: half C = silu(Res)*acc    EPI 3: half C = alpha*acc
// EPI 4: half Ct[col][row] = acc (transposed, ldct)
template <int EPI, int BN>
__global__ __launch_bounds__(256, (BN == 128) ? 2 : 1) void gemm_h(
    const __half* __restrict__ A, const __half* __restrict__ B,
    void* __restrict__ Cv, const float* __restrict__ Res,
    int M, int N, int K, int lda, int ldb, int ldc, float alpha,
    int bh, long sAb, long sAh, long sBb, long sBh, long sCb, long sCh,
    int ldct)
{
    constexpr int WN = BN / 4;
    constexpr int NT = WN / 8;
    constexpr int NP = WN / 16;
    constexpr uint32_t STAGE = (uint32_t)(128 + BN) * 128u;

    extern __shared__ char smem[];
    uint32_t sb = (uint32_t)__cvta_generic_to_shared(smem);

    int tid = threadIdx.x;
    int wid = tid >> 5, l = tid & 31;
    int wr = wid & 1, wc = wid >> 1;

    int z  = blockIdx.z;
    int zb = z / bh, zh = z % bh;
    A += (size_t)zb * sAb + (size_t)zh * sAh;
    B += (size_t)zb * sBb + (size_t)zh * sBh;
    float*  Cf = (float*)Cv  + (size_t)zb * sCb + (size_t)zh * sCh;
    __half* Ch = (__half*)Cv + (size_t)zb * sCb + (size_t)zh * sCh;
    if (EPI == 1 || EPI == 2) Res += (size_t)zb * sCb + (size_t)zh * sCh;

    int m0 = blockIdx.y * 128, n0 = blockIdx.x * BN;

    auto load_chunk = [&](int stage, int k0) {
        uint32_t ab = sb + (uint32_t)stage * STAGE;
        uint32_t bb = ab + 16384u;
#pragma unroll
        for (int i = 0; i < 4; i++) {
            int s = tid + i * 256;
            int r = s >> 3, c16 = s & 7;
            uint32_t off = (uint32_t)(r * 128 + ((c16 * 16) ^ ((r & 7) << 4)));
            cpasync16(ab + off, &A[(size_t)(m0 + r) * lda + k0 + c16 * 8]);
        }
#pragma unroll
        for (int i = 0; i < BN / 32; i++) {
            int s = tid + i * 256;
            int r = s >> 3, c16 = s & 7;
            uint32_t off = (uint32_t)(r * 128 + ((c16 * 16) ^ ((r & 7) << 4)));
            cpasync16(bb + off, &B[(size_t)(n0 + r) * ldb + k0 + c16 * 8]);
        }
        asm volatile("cp.async.commit_group;" ::: "memory");
    };

    float d[4][NT][4];
#pragma unroll
    for (int i = 0; i < 4; i++)
#pragma unroll
        for (int j = 0; j < NT; j++)
#pragma unroll
            for (int q = 0; q < 4; q++) d[i][j][q] = 0.f;

    int arow = wr * 64 + (l & 15);
    int brow = wc * WN + (l & 7) + (((l >> 4) & 1) << 3);
    uint32_t xm  = (uint32_t)((l & 7) << 4);
    uint32_t cba_sel = (uint32_t)(((l >> 4) & 1) << 4);
    uint32_t cbb_sel = (uint32_t)(((l >> 3) & 1) << 4);

    int nch = K >> 6;
    load_chunk(0, 0);
    if (nch > 1) load_chunk(1, 64);

    int stage = 0;
    for (int i = 0; i < nch; i++) {
        if (i + 1 < nch)
            asm volatile("cp.async.wait_group 1;" ::: "memory");
        else
            asm volatile("cp.async.wait_group 0;" ::: "memory");
        __syncthreads();
        if (i + 2 < nch) {
            int ns = stage + 2; if (ns >= 3) ns -= 3;
            load_chunk(ns, (i + 2) << 6);
        }

        uint32_t abase = sb + (uint32_t)stage * STAGE + (uint32_t)(arow * 128);
        uint32_t bbase = sb + (uint32_t)stage * STAGE + 16384u + (uint32_t)(brow * 128);
#pragma unroll
        for (int kk = 0; kk < 4; kk++) {
            uint32_t cba = ((uint32_t)(kk * 32) + cba_sel) ^ xm;
            uint32_t cbb = ((uint32_t)(kk * 32) + cbb_sel) ^ xm;
            uint32_t af[4][4], bf[NP][4];
#pragma unroll
            for (int mt = 0; mt < 4; mt++)
                ldsm4(af[mt], abase + (uint32_t)(mt * 2048) + cba);
#pragma unroll
            for (int p = 0; p < NP; p++)
                ldsm4(bf[p], bbase + (uint32_t)(p * 2048) + cbb);
#pragma unroll
            for (int mt = 0; mt < 4; mt++)
#pragma unroll
                for (int nt = 0; nt < NT; nt++)
                    mma16(d[mt][nt], af[mt], &bf[nt >> 1][(nt & 1) * 2]);
        }
        stage++; if (stage >= 3) stage -= 3;
    }
    __syncthreads();

    int g = l >> 2, q4 = l & 3;
#pragma unroll
    for (int mt = 0; mt < 4; mt++) {
#pragma unroll
        for (int nt = 0; nt < NT; nt++) {
#pragma unroll
            for (int half = 0; half < 2; half++) {
                int row = m0 + wr * 64 + mt * 16 + g + half * 8;
                int col = n0 + wc * WN + nt * 8 + q4 * 2;
                float v0 = d[mt][nt][half * 2 + 0] * alpha;
                float v1 = d[mt][nt][half * 2 + 1] * alpha;
                if (EPI == 4) {
                    Ch[(size_t)col       * ldct + row] = __float2half(v0);
                    Ch[(size_t)(col + 1) * ldct + row] = __float2half(v1);
                } else if (EPI == 0) {
                    *reinterpret_cast<float2*>(&Cf[(size_t)row * ldc + col]) =
                        make_float2(v0, v1);
                } else if (EPI == 1) {
                    float2 r = *reinterpret_cast<const float2*>(
                        &Res[(size_t)row * ldc + col]);
                    *reinterpret_cast<float2*>(&Cf[(size_t)row * ldc + col]) =
                        make_float2(v0 + r.x, v1 + r.y);
                } else if (EPI == 2) {
                    float2 gg = *reinterpret_cast<const float2*>(
                        &Res[(size_t)row * ldc + col]);
                    float s0 = v0 * gg.x / (1.f + expf(-gg.x));
                    float s1 = v1 * gg.y / (1.f + expf(-gg.y));
                    *reinterpret_cast<__half2*>(&Ch[(size_t)row * ldc + col]) =
                        __floats2half2_rn(s0, s1);
                } else {
                    *reinterpret_cast<__half2*>(&Ch[(size_t)row * ldc + col]) =
                        __floats2half2_rn(v0, v1);
                }
            }
        }
    }
}

#define SM256 (3 * (128 + 256) * 128)   // 147456

// ---------------- launch ------------------------------------------------------
extern "C" void kernel_launch(void* const* d_in, const int* in_sizes, int n_in,
                              void* d_out, int out_size)
{
    const float* x   = (const float*)d_in[0];
    const float* wq  = (const float*)d_in[1];
    const float* wk  = (const float*)d_in[2];
    const float* wv  = (const float*)d_in[3];
    const float* wo  = (const float*)d_in[4];
    const float* wg  = (const float*)d_in[5];
    const float* wu  = (const float*)d_in[6];
    const float* wd  = (const float*)d_in[7];
    const float* l1w = (const float*)d_in[8];
    const float* l1b = (const float*)d_in[9];
    const float* l2w = (const float*)d_in[10];
    const float* l2b = (const float*)d_in[11];
    float* out = (float*)d_out;

    __half *ln, *q, *k, *vt, *att, *hid;
    float *x1, *gate;
    __half *wqh, *wkh, *wvh, *woh, *wgh, *wuh, *wdh;
    cudaGetSymbolAddress((void**)&ln,   g_ln);
    cudaGetSymbolAddress((void**)&q,    g_q);
    cudaGetSymbolAddress((void**)&k,    g_k);
    cudaGetSymbolAddress((void**)&vt,   g_vt);
    cudaGetSymbolAddress((void**)&att,  g_att);
    cudaGetSymbolAddress((void**)&x1,   g_x1);
    cudaGetSymbolAddress((void**)&gate, g_gate);
    cudaGetSymbolAddress((void**)&hid,  g_hid);
    cudaGetSymbolAddress((void**)&wqh,  g_wqh);
    cudaGetSymbolAddress((void**)&wkh,  g_wkh);
    cudaGetSymbolAddress((void**)&wvh,  g_wvh);
    cudaGetSymbolAddress((void**)&woh,  g_woh);
    cudaGetSymbolAddress((void**)&wgh,  g_wgh);
    cudaGetSymbolAddress((void**)&wuh,  g_wuh);
    cudaGetSymbolAddress((void**)&wdh,  g_wdh);

    cudaFuncSetAttribute(gemm_h<0,256>, cudaFuncAttributeMaxDynamicSharedMemorySize, SM256);
    cudaFuncSetAttribute(gemm_h<1,256>, cudaFuncAttributeMaxDynamicSharedMemorySize, SM256);
    cudaFuncSetAttribute(gemm_h<2,256>, cudaFuncAttributeMaxDynamicSharedMemorySize, SM256);
    cudaFuncSetAttribute(gemm_h<3,256>, cudaFuncAttributeMaxDynamicSharedMemorySize, SM256);
    cudaFuncSetAttribute(gemm_h<4,256>, cudaFuncAttributeMaxDynamicSharedMemorySize, SM256);
    cudaFuncSetAttribute(fattn_kernel, cudaFuncAttributeMaxDynamicSharedMemorySize, FA_SMEM);

    dim3 blk(256);

    // weight converts
    cvt_kernel<<<1024, blk>>>(wq, wqh, DM * DM);
    cvt_kernel<<<1024, blk>>>(wk, wkh, DM * DM);
    cvt_kernel<<<1024, blk>>>(wv, wvh, DM * DM);
    cvt_kernel<<<1024, blk>>>(wo, woh, DM * DM);

    // LN1
    ln_kernel<<<MTOK, blk>>>(x, l1w, l1b, ln);

    // Q (alpha folds log2e/sqrt(dh)), K, V^T
    dim3 gp(DM / 256, MTOK / 128, 1);
    gemm_h<3,256><<<gp, blk, SM256>>>(ln, wqh, q, nullptr, MTOK, DM, DM,
                                      DM, DM, DM, LOG2E / sqrtf((float)DH),
                                      1, 0, 0, 0, 0, 0, 0, 0);
    gemm_h<3,256><<<gp, blk, SM256>>>(ln, wkh, k, nullptr, MTOK, DM, DM,
                                      DM, DM, DM, 1.f, 1, 0, 0, 0, 0, 0, 0, 0);
    gemm_h<4,256><<<gp, blk, SM256>>>(ln, wvh, vt, nullptr, MTOK, DM, DM,
                                      DM, DM, DM, 1.f, 1, 0, 0, 0, 0, 0, 0, MTOK);

    // MLP weight converts
    cvt_kernel<<<2048, blk>>>(wg, wgh, FF * DM);
    cvt_kernel<<<2048, blk>>>(wu, wuh, FF * DM);
    cvt_kernel<<<2048, blk>>>(wd, wdh, DM * FF);

    // fused attention: scores + softmax + P·V
    dim3 ga(T / 128, BSZ * NH);
    fattn_kernel<<<ga, blk, FA_SMEM>>>(q, k, vt, att);

    // x1 = x + att @ wo^T
    gemm_h<1,256><<<gp, blk, SM256>>>(att, woh, x1, x, MTOK, DM, DM,
                                      DM, DM, DM, 1.f, 1, 0, 0, 0, 0, 0, 0, 0);

    // LN2
    ln_kernel<<<MTOK, blk>>>(x1, l2w, l2b, ln);

    // gate = ln @ wg^T (fp32 out)
    dim3 gf(FF / 256, MTOK / 128, 1);
    gemm_h<0,256><<<gf, blk, SM256>>>(ln, wgh, gate, nullptr, MTOK, FF, DM,
                                      DM, DM, FF, 1.f, 1, 0, 0, 0, 0, 0, 0, 0);

    // hid = silu(gate) * (ln @ wu^T) (fp16 out)
    gemm_h<2,256><<<gf, blk, SM256>>>(ln, wuh, hid, gate, MTOK, FF, DM,
                                      DM, DM, FF, 1.f, 1, 0, 0, 0, 0, 0, 0, 0);

    // out = x1 + hid @ wd^T
    dim3 gd(DM / 256, MTOK / 128, 1);
    gemm_h<1,256><<<gd, blk, SM256>>>(hid, wdh, out, x1, MTOK, DM, FF,
                                      FF, FF, DM, 1.f, 1, 0, 0, 0, 0, 0, 0, 0);
}

// round 8
// speedup vs baseline: 1.5049x; 1.5049x over previous
#include <cuda_runtime.h>
#include <cuda_fp16.h>
#include <math.h>
#include <cstdint>
#include <cstddef>

#define BSZ   2
#define T     2048
#define DM    2048
#define NH    16
#define DH    128
#define FF    8192
#define MTOK  (BSZ*T)
#define LNEPS 1e-5f
#define LOG2E 1.4426950408889634f

// ---------------- scratch ----------------------------------------------------
__device__ __align__(128) __half g_ln  [(size_t)MTOK*DM];
__device__ __align__(128) __half g_q   [(size_t)MTOK*DM];
__device__ __align__(128) __half g_k   [(size_t)MTOK*DM];
__device__ __align__(128) __half g_vt  [(size_t)DM*MTOK];   // V^T [DM][MTOK]
__device__ __align__(128) __half g_att [(size_t)MTOK*DM];
__device__ __align__(128) float  g_x1  [(size_t)MTOK*DM];
__device__ __align__(128) float  g_gate[(size_t)MTOK*FF];
__device__ __align__(128) __half g_hid [(size_t)MTOK*FF];
__device__ __align__(128) __half g_wqh [(size_t)DM*DM];
__device__ __align__(128) __half g_wkh [(size_t)DM*DM];
__device__ __align__(128) __half g_wvh [(size_t)DM*DM];
__device__ __align__(128) __half g_woh [(size_t)DM*DM];
__device__ __align__(128) __half g_wgh [(size_t)FF*DM];
__device__ __align__(128) __half g_wuh [(size_t)FF*DM];
__device__ __align__(128) __half g_wdh [(size_t)DM*FF];

// ---------------- helpers ----------------------------------------------------
__device__ __forceinline__ void cpasync16(uint32_t dst, const void* src) {
    asm volatile("cp.async.cg.shared.global [%0], [%1], 16;\n"
                 :: "r"(dst), "l"(__cvta_generic_to_global(src)) : "memory");
}

__device__ __forceinline__ void ldsm4(uint32_t* r, uint32_t addr) {
    asm volatile("ldmatrix.sync.aligned.m8n8.x4.shared.b16 {%0,%1,%2,%3}, [%4];"
                 : "=r"(r[0]), "=r"(r[1]), "=r"(r[2]), "=r"(r[3]) : "r"(addr));
}

__device__ __forceinline__ void mma16(float* d, const uint32_t* a, const uint32_t* b) {
    asm volatile(
        "mma.sync.aligned.m16n8k16.row.col.f32.f16.f16.f32 "
        "{%0,%1,%2,%3}, {%4,%5,%6,%7}, {%8,%9}, {%0,%1,%2,%3};"
        : "+f"(d[0]), "+f"(d[1]), "+f"(d[2]), "+f"(d[3])
        : "r"(a[0]), "r"(a[1]), "r"(a[2]), "r"(a[3]), "r"(b[0]), "r"(b[1]));
}

// ---------------- fp32 -> fp16 convert ----------------------------------------
__global__ __launch_bounds__(256) void cvt_kernel(const float* __restrict__ in,
                                                  __half* __restrict__ o, int n) {
    int n8 = n >> 3;
    for (int i = blockIdx.x * 256 + threadIdx.x; i < n8; i += gridDim.x * 256) {
        float4 a = reinterpret_cast<const float4*>(in)[2 * i];
        float4 b = reinterpret_cast<const float4*>(in)[2 * i + 1];
        __half2 h0 = __floats2half2_rn(a.x, a.y);
        __half2 h1 = __floats2half2_rn(a.z, a.w);
        __half2 h2 = __floats2half2_rn(b.x, b.y);
        __half2 h3 = __floats2half2_rn(b.z, b.w);
        uint4 u;
        u.x = *reinterpret_cast<uint32_t*>(&h0);
        u.y = *reinterpret_cast<uint32_t*>(&h1);
        u.z = *reinterpret_cast<uint32_t*>(&h2);
        u.w = *reinterpret_cast<uint32_t*>(&h3);
        reinterpret_cast<uint4*>(o)[i] = u;
    }
}

// ---------------- LayerNorm (fp16 output) -------------------------------------
__global__ __launch_bounds__(256) void ln_kernel(
    const float* __restrict__ x, const float* __restrict__ w,
    const float* __restrict__ b, __half* __restrict__ y)
{
    int row = blockIdx.x;
    const float* xr = x + (size_t)row * DM;
    float v[8];
    float s = 0.f, ss = 0.f;
#pragma unroll
    for (int i = 0; i < 8; i++) {
        float t = xr[threadIdx.x + 256 * i];
        v[i] = t; s += t; ss += t * t;
    }
    __shared__ float r1[256], r2[256];
    r1[threadIdx.x] = s; r2[threadIdx.x] = ss;
    __syncthreads();
    for (int off = 128; off > 0; off >>= 1) {
        if (threadIdx.x < off) {
            r1[threadIdx.x] += r1[threadIdx.x + off];
            r2[threadIdx.x] += r2[threadIdx.x + off];
        }
        __syncthreads();
    }
    float mu  = r1[0] * (1.f / DM);
    float var = r2[0] * (1.f / DM) - mu * mu;
    float rstd = rsqrtf(var + LNEPS);
    __half* yr = y + (size_t)row * DM;
#pragma unroll
    for (int i = 0; i < 8; i++) {
        int c = threadIdx.x + 256 * i;
        yr[c] = __float2half((v[i] - mu) * rstd * w[c] + b[c]);
    }
}

// ---------------- fused flash attention (KV tile = 64 keys) --------------------
// q: [MTOK][DM] fp16, logits pre-scaled by log2e/sqrt(DH) (folded into Q proj)
// k: [MTOK][DM] fp16; vt: [DM][MTOK] fp16; out att: [MTOK][DM] fp16
// CTA: 128 q-rows of one (b,h); 8 warps x 16 q-rows; 32 KV iterations.
// smem: Q 32KB (two 16KB dh-chunks) + 2 stages x (K 16KB + V 16KB) = 96KB.
#define FA_SMEM (32768 + 2 * 32768)
__global__ __launch_bounds__(256, 1) void fattn_kernel(
    const __half* __restrict__ q, const __half* __restrict__ k,
    const __half* __restrict__ vt, __half* __restrict__ att)
{
    extern __shared__ char smem[];
    uint32_t sb = (uint32_t)__cvta_generic_to_shared(smem);
    int tid = threadIdx.x, wid = tid >> 5, l = tid & 31;

    int z = blockIdx.y;
    int b = z / NH, h = z % NH;
    int q0 = blockIdx.x * 128;
    const __half* Qp = q  + ((size_t)(b * T + q0)) * DM + h * DH;
    const __half* Kp = k  + ((size_t)(b * T)) * DM + h * DH;
    const __half* Vp = vt + ((size_t)(h * DH)) * MTOK + (size_t)b * T;
    __half* Op = att + ((size_t)(b * T + q0)) * DM + h * DH;

    // Q tile: 128 rows x 128 halves = two [128][64] chunks at sb+0, sb+16K
#pragma unroll
    for (int i = 0; i < 8; i++) {
        int s = tid + i * 256;
        int r = s >> 4, u = s & 15;
        int ch = u >> 3, c16 = u & 7;
        uint32_t off = (uint32_t)(ch * 16384 + r * 128 + ((c16 * 16) ^ ((r & 7) << 4)));
        cpasync16(sb + off, Qp + (size_t)r * DM + u * 8);
    }
    asm volatile("cp.async.commit_group;" ::: "memory");

    // K stage: [64 keys][128 dh halves] = two [64][64] 8KB chunks
    // V stage: [128 dh][64 keys] = 128 rows x 128B (single chunk)
    auto load_kv = [&](int buf, int kt) {
        uint32_t kb_ = sb + 32768u + (uint32_t)buf * 32768u;
        uint32_t vb_ = kb_ + 16384u;
#pragma unroll
        for (int i = 0; i < 4; i++) {
            int s = tid + i * 256;
            int r = s >> 4, u = s & 15;          // r 0..63 keys, u 0..15
            int ch = u >> 3, c16 = u & 7;
            uint32_t off = (uint32_t)(ch * 8192 + r * 128 + ((c16 * 16) ^ ((r & 7) << 4)));
            cpasync16(kb_ + off, Kp + (size_t)(kt * 64 + r) * DM + u * 8);
        }
#pragma unroll
        for (int i = 0; i < 4; i++) {
            int s = tid + i * 256;
            int r = s >> 3, u = s & 7;           // r 0..127 dh, u 0..7
            uint32_t off = (uint32_t)(r * 128 + ((u * 16) ^ ((r & 7) << 4)));
            cpasync16(vb_ + off, Vp + (size_t)r * MTOK + kt * 64 + u * 8);
        }
        asm volatile("cp.async.commit_group;" ::: "memory");
    };
    load_kv(0, 0);

    asm volatile("cp.async.wait_group 1;" ::: "memory");   // Q ready
    __syncthreads();

    uint32_t xm    = (uint32_t)((l & 7) << 4);
    uint32_t cselA = (uint32_t)(((l >> 4) & 1) << 4);
    uint32_t cselB = (uint32_t)(((l >> 3) & 1) << 4);
    int brlo = (l & 7) + (((l >> 4) & 1) << 3);

    uint32_t qf[8][4];
    {
        int arow = wid * 16 + (l & 15);
        uint32_t base = sb + (uint32_t)(arow * 128);
#pragma unroll
        for (int kb = 0; kb < 8; kb++) {
            int ch = kb >> 2, kk = kb & 3;
            ldsm4(qf[kb], base + (uint32_t)(ch * 16384) + (((uint32_t)(kk * 32) + cselA) ^ xm));
        }
    }

    float O[16][4];
#pragma unroll
    for (int i = 0; i < 16; i++)
#pragma unroll
        for (int j = 0; j < 4; j++) O[i][j] = 0.f;
    float m0 = -1e30f, m1 = -1e30f, l0 = 0.f, l1 = 0.f;

    const int NIT = T / 64;
    for (int it = 0; it < NIT; it++) {
        int cur = it & 1;
        if (it + 1 < NIT) {
            load_kv(cur ^ 1, it + 1);
            asm volatile("cp.async.wait_group 1;" ::: "memory");
        } else {
            asm volatile("cp.async.wait_group 0;" ::: "memory");
        }
        __syncthreads();

        uint32_t kbase = sb + 32768u + (uint32_t)cur * 32768u;
        uint32_t vbase = kbase + 16384u;

        // S[16 rows][64 keys] per warp; 8 key-subtiles of 8
        float S[8][4];
#pragma unroll
        for (int i = 0; i < 8; i++)
#pragma unroll
            for (int j = 0; j < 4; j++) S[i][j] = 0.f;
#pragma unroll
        for (int kb = 0; kb < 8; kb++) {            // dh chunks of 16
            int ch = kb >> 2, kk = kb & 3;
            uint32_t kcol = kbase + (uint32_t)(ch * 8192) + (((uint32_t)(kk * 32) + cselB) ^ xm);
#pragma unroll
            for (int ng = 0; ng < 4; ng++) {        // key groups of 16
                uint32_t bf[4];
                ldsm4(bf, kcol + (uint32_t)((ng * 16 + brlo) * 128));
                mma16(S[2 * ng],     qf[kb], &bf[0]);
                mma16(S[2 * ng + 1], qf[kb], &bf[2]);
            }
        }

        // online softmax (base-2)
        float mx0 = -1e30f, mx1 = -1e30f;
#pragma unroll
        for (int nt = 0; nt < 8; nt++) {
            mx0 = fmaxf(mx0, fmaxf(S[nt][0], S[nt][1]));
            mx1 = fmaxf(mx1, fmaxf(S[nt][2], S[nt][3]));
        }
        mx0 = fmaxf(mx0, __shfl_xor_sync(0xffffffffu, mx0, 1));
        mx0 = fmaxf(mx0, __shfl_xor_sync(0xffffffffu, mx0, 2));
        mx1 = fmaxf(mx1, __shfl_xor_sync(0xffffffffu, mx1, 1));
        mx1 = fmaxf(mx1, __shfl_xor_sync(0xffffffffu, mx1, 2));
        float mn0 = fmaxf(m0, mx0), mn1 = fmaxf(m1, mx1);
        float sc0 = exp2f(m0 - mn0), sc1 = exp2f(m1 - mn1);
        m0 = mn0; m1 = mn1;
        l0 *= sc0; l1 *= sc1;
#pragma unroll
        for (int nt = 0; nt < 16; nt++) {
            O[nt][0] *= sc0; O[nt][1] *= sc0;
            O[nt][2] *= sc1; O[nt][3] *= sc1;
        }
#pragma unroll
        for (int nt = 0; nt < 8; nt++) {
            S[nt][0] = exp2f(S[nt][0] - mn0);
            S[nt][1] = exp2f(S[nt][1] - mn0);
            S[nt][2] = exp2f(S[nt][2] - mn1);
            S[nt][3] = exp2f(S[nt][3] - mn1);
            l0 += S[nt][0] + S[nt][1];
            l1 += S[nt][2] + S[nt][3];
        }

        // O += P V   (P in-register as fp16 A-frags; k = 64 keys = 4 chunks)
#pragma unroll
        for (int kb = 0; kb < 4; kb++) {
            uint32_t pa[4];
            __half2 h0 = __floats2half2_rn(S[2 * kb][0],     S[2 * kb][1]);
            __half2 h1 = __floats2half2_rn(S[2 * kb][2],     S[2 * kb][3]);
            __half2 h2 = __floats2half2_rn(S[2 * kb + 1][0], S[2 * kb + 1][1]);
            __half2 h3 = __floats2half2_rn(S[2 * kb + 1][2], S[2 * kb + 1][3]);
            pa[0] = *reinterpret_cast<uint32_t*>(&h0);
            pa[1] = *reinterpret_cast<uint32_t*>(&h1);
            pa[2] = *reinterpret_cast<uint32_t*>(&h2);
            pa[3] = *reinterpret_cast<uint32_t*>(&h3);
            uint32_t vcol = vbase + (((uint32_t)(kb * 32) + cselB) ^ xm);
#pragma unroll
            for (int ng = 0; ng < 8; ng++) {        // dh groups of 16
                uint32_t bf[4];
                ldsm4(bf, vcol + (uint32_t)((ng * 16 + brlo) * 128));
                mma16(O[2 * ng],     pa, &bf[0]);
                mma16(O[2 * ng + 1], pa, &bf[2]);
            }
        }
        __syncthreads();
    }

    l0 += __shfl_xor_sync(0xffffffffu, l0, 1);
    l0 += __shfl_xor_sync(0xffffffffu, l0, 2);
    l1 += __shfl_xor_sync(0xffffffffu, l1, 1);
    l1 += __shfl_xor_sync(0xffffffffu, l1, 2);
    float inv0 = 1.f / l0, inv1 = 1.f / l1;

    int g = l >> 2, q4 = l & 3;
#pragma unroll
    for (int nt = 0; nt < 16; nt++) {
        int c = nt * 8 + q4 * 2;
        *reinterpret_cast<__half2*>(&Op[(size_t)(wid * 16 + g) * DM + c]) =
            __floats2half2_rn(O[nt][0] * inv0, O[nt][1] * inv0);
        *reinterpret_cast<__half2*>(&Op[(size_t)(wid * 16 + g + 8) * DM + c]) =
            __floats2half2_rn(O[nt][2] * inv1, O[nt][3] * inv1);
    }
}

// ---------------- fp16 mma.sync NT GEMM ---------------------------------------
// EPI 0: float C = alpha*acc       EPI 1: float C = Res + alpha*acc
// EPI 2: half C = silu(Res)*acc    EPI 3: half C = alpha*acc
// EPI 4: half Ct[col][row] = acc (transposed, ldct)
template <int EPI, int BN>
__global__ __launch_bounds__(256, (BN == 128) ? 2 : 1) void gemm_h(
    const __half* __restrict__ A, const __half* __restrict__ B,
    void* __restrict__ Cv, const float* __restrict__ Res,
    int M, int N, int K, int lda, int ldb, int ldc, float alpha,
    int bh, long sAb, long sAh, long sBb, long sBh, long sCb, long sCh,
    int ldct)
{
    constexpr int WN = BN / 4;
    constexpr int NT = WN / 8;
    constexpr int NP = WN / 16;
    constexpr uint32_t STAGE = (uint32_t)(128 + BN) * 128u;

    extern __shared__ char smem[];
    uint32_t sb = (uint32_t)__cvta_generic_to_shared(smem);

    int tid = threadIdx.x;
    int wid = tid >> 5, l = tid & 31;
    int wr = wid & 1, wc = wid >> 1;

    int z  = blockIdx.z;
    int zb = z / bh, zh = z % bh;
    A += (size_t)zb * sAb + (size_t)zh * sAh;
    B += (size_t)zb * sBb + (size_t)zh * sBh;
    float*  Cf = (float*)Cv  + (size_t)zb * sCb + (size_t)zh * sCh;
    __half* Ch = (__half*)Cv + (size_t)zb * sCb + (size_t)zh * sCh;
    if (EPI == 1 || EPI == 2) Res += (size_t)zb * sCb + (size_t)zh * sCh;

    int m0 = blockIdx.y * 128, n0 = blockIdx.x * BN;

    auto load_chunk = [&](int stage, int k0) {
        uint32_t ab = sb + (uint32_t)stage * STAGE;
        uint32_t bb = ab + 16384u;
#pragma unroll
        for (int i = 0; i < 4; i++) {
            int s = tid + i * 256;
            int r = s >> 3, c16 = s & 7;
            uint32_t off = (uint32_t)(r * 128 + ((c16 * 16) ^ ((r & 7) << 4)));
            cpasync16(ab + off, &A[(size_t)(m0 + r) * lda + k0 + c16 * 8]);
        }
#pragma unroll
        for (int i = 0; i < BN / 32; i++) {
            int s = tid + i * 256;
            int r = s >> 3, c16 = s & 7;
            uint32_t off = (uint32_t)(r * 128 + ((c16 * 16) ^ ((r & 7) << 4)));
            cpasync16(bb + off, &B[(size_t)(n0 + r) * ldb + k0 + c16 * 8]);
        }
        asm volatile("cp.async.commit_group;" ::: "memory");
    };

    float d[4][NT][4];
#pragma unroll
    for (int i = 0; i < 4; i++)
#pragma unroll
        for (int j = 0; j < NT; j++)
#pragma unroll
            for (int q = 0; q < 4; q++) d[i][j][q] = 0.f;

    int arow = wr * 64 + (l & 15);
    int brow = wc * WN + (l & 7) + (((l >> 4) & 1) << 3);
    uint32_t xm  = (uint32_t)((l & 7) << 4);
    uint32_t cba_sel = (uint32_t)(((l >> 4) & 1) << 4);
    uint32_t cbb_sel = (uint32_t)(((l >> 3) & 1) << 4);

    int nch = K >> 6;
    load_chunk(0, 0);
    if (nch > 1) load_chunk(1, 64);

    int stage = 0;
    for (int i = 0; i < nch; i++) {
        if (i + 1 < nch)
            asm volatile("cp.async.wait_group 1;" ::: "memory");
        else
            asm volatile("cp.async.wait_group 0;" ::: "memory");
        __syncthreads();
        if (i + 2 < nch) {
            int ns = stage + 2; if (ns >= 3) ns -= 3;
            load_chunk(ns, (i + 2) << 6);
        }

        uint32_t abase = sb + (uint32_t)stage * STAGE + (uint32_t)(arow * 128);
        uint32_t bbase = sb + (uint32_t)stage * STAGE + 16384u + (uint32_t)(brow * 128);
#pragma unroll
        for (int kk = 0; kk < 4; kk++) {
            uint32_t cba = ((uint32_t)(kk * 32) + cba_sel) ^ xm;
            uint32_t cbb = ((uint32_t)(kk * 32) + cbb_sel) ^ xm;
            uint32_t af[4][4], bf[NP][4];
#pragma unroll
            for (int mt = 0; mt < 4; mt++)
                ldsm4(af[mt], abase + (uint32_t)(mt * 2048) + cba);
#pragma unroll
            for (int p = 0; p < NP; p++)
                ldsm4(bf[p], bbase + (uint32_t)(p * 2048) + cbb);
#pragma unroll
            for (int mt = 0; mt < 4; mt++)
#pragma unroll
                for (int nt = 0; nt < NT; nt++)
                    mma16(d[mt][nt], af[mt], &bf[nt >> 1][(nt & 1) * 2]);
        }
        stage++; if (stage >= 3) stage -= 3;
    }
    __syncthreads();

    int g = l >> 2, q4 = l & 3;
#pragma unroll
    for (int mt = 0; mt < 4; mt++) {
#pragma unroll
        for (int nt = 0; nt < NT; nt++) {
#pragma unroll
            for (int half = 0; half < 2; half++) {
                int row = m0 + wr * 64 + mt * 16 + g + half * 8;
                int col = n0 + wc * WN + nt * 8 + q4 * 2;
                float v0 = d[mt][nt][half * 2 + 0] * alpha;
                float v1 = d[mt][nt][half * 2 + 1] * alpha;
                if (EPI == 4) {
                    Ch[(size_t)col       * ldct + row] = __float2half(v0);
                    Ch[(size_t)(col + 1) * ldct + row] = __float2half(v1);
                } else if (EPI == 0) {
                    *reinterpret_cast<float2*>(&Cf[(size_t)row * ldc + col]) =
                        make_float2(v0, v1);
                } else if (EPI == 1) {
                    float2 r = *reinterpret_cast<const float2*>(
                        &Res[(size_t)row * ldc + col]);
                    *reinterpret_cast<float2*>(&Cf[(size_t)row * ldc + col]) =
                        make_float2(v0 + r.x, v1 + r.y);
                } else if (EPI == 2) {
                    float2 gg = *reinterpret_cast<const float2*>(
                        &Res[(size_t)row * ldc + col]);
                    float s0 = v0 * gg.x / (1.f + expf(-gg.x));
                    float s1 = v1 * gg.y / (1.f + expf(-gg.y));
                    *reinterpret_cast<__half2*>(&Ch[(size_t)row * ldc + col]) =
                        __floats2half2_rn(s0, s1);
                } else {
                    *reinterpret_cast<__half2*>(&Ch[(size_t)row * ldc + col]) =
                        __floats2half2_rn(v0, v1);
                }
            }
        }
    }
}

#define SM256 (3 * (128 + 256) * 128)   // 147456

// ---------------- launch ------------------------------------------------------
extern "C" void kernel_launch(void* const* d_in, const int* in_sizes, int n_in,
                              void* d_out, int out_size)
{
    const float* x   = (const float*)d_in[0];
    const float* wq  = (const float*)d_in[1];
    const float* wk  = (const float*)d_in[2];
    const float* wv  = (const float*)d_in[3];
    const float* wo  = (const float*)d_in[4];
    const float* wg  = (const float*)d_in[5];
    const float* wu  = (const float*)d_in[6];
    const float* wd  = (const float*)d_in[7];
    const float* l1w = (const float*)d_in[8];
    const float* l1b = (const float*)d_in[9];
    const float* l2w = (const float*)d_in[10];
    const float* l2b = (const float*)d_in[11];
    float* out = (float*)d_out;

    __half *ln, *q, *k, *vt, *att, *hid;
    float *x1, *gate;
    __half *wqh, *wkh, *wvh, *woh, *wgh, *wuh, *wdh;
    cudaGetSymbolAddress((void**)&ln,   g_ln);
    cudaGetSymbolAddress((void**)&q,    g_q);
    cudaGetSymbolAddress((void**)&k,    g_k);
    cudaGetSymbolAddress((void**)&vt,   g_vt);
    cudaGetSymbolAddress((void**)&att,  g_att);
    cudaGetSymbolAddress((void**)&x1,   g_x1);
    cudaGetSymbolAddress((void**)&gate, g_gate);
    cudaGetSymbolAddress((void**)&hid,  g_hid);
    cudaGetSymbolAddress((void**)&wqh,  g_wqh);
    cudaGetSymbolAddress((void**)&wkh,  g_wkh);
    cudaGetSymbolAddress((void**)&wvh,  g_wvh);
    cudaGetSymbolAddress((void**)&woh,  g_woh);
    cudaGetSymbolAddress((void**)&wgh,  g_wgh);
    cudaGetSymbolAddress((void**)&wuh,  g_wuh);
    cudaGetSymbolAddress((void**)&wdh,  g_wdh);

    cudaFuncSetAttribute(gemm_h<0,256>, cudaFuncAttributeMaxDynamicSharedMemorySize, SM256);
    cudaFuncSetAttribute(gemm_h<1,256>, cudaFuncAttributeMaxDynamicSharedMemorySize, SM256);
    cudaFuncSetAttribute(gemm_h<2,256>, cudaFuncAttributeMaxDynamicSharedMemorySize, SM256);
    cudaFuncSetAttribute(gemm_h<3,256>, cudaFuncAttributeMaxDynamicSharedMemorySize, SM256);
    cudaFuncSetAttribute(gemm_h<4,256>, cudaFuncAttributeMaxDynamicSharedMemorySize, SM256);
    cudaFuncSetAttribute(fattn_kernel, cudaFuncAttributeMaxDynamicSharedMemorySize, FA_SMEM);

    dim3 blk(256);

    // weight converts
    cvt_kernel<<<1024, blk>>>(wq, wqh, DM * DM);
    cvt_kernel<<<1024, blk>>>(wk, wkh, DM * DM);
    cvt_kernel<<<1024, blk>>>(wv, wvh, DM * DM);
    cvt_kernel<<<1024, blk>>>(wo, woh, DM * DM);

    // LN1
    ln_kernel<<<MTOK, blk>>>(x, l1w, l1b, ln);

    // Q (alpha folds log2e/sqrt(dh)), K, V^T
    dim3 gp(DM / 256, MTOK / 128, 1);
    gemm_h<3,256><<<gp, blk, SM256>>>(ln, wqh, q, nullptr, MTOK, DM, DM,
                                      DM, DM, DM, LOG2E / sqrtf((float)DH),
                                      1, 0, 0, 0, 0, 0, 0, 0);
    gemm_h<3,256><<<gp, blk, SM256>>>(ln, wkh, k, nullptr, MTOK, DM, DM,
                                      DM, DM, DM, 1.f, 1, 0, 0, 0, 0, 0, 0, 0);
    gemm_h<4,256><<<gp, blk, SM256>>>(ln, wvh, vt, nullptr, MTOK, DM, DM,
                                      DM, DM, DM, 1.f, 1, 0, 0, 0, 0, 0, 0, MTOK);

    // MLP weight converts
    cvt_kernel<<<2048, blk>>>(wg, wgh, FF * DM);
    cvt_kernel<<<2048, blk>>>(wu, wuh, FF * DM);
    cvt_kernel<<<2048, blk>>>(wd, wdh, DM * FF);

    // fused attention
    dim3 ga(T / 128, BSZ * NH);
    fattn_kernel<<<ga, blk, FA_SMEM>>>(q, k, vt, att);

    // x1 = x + att @ wo^T
    gemm_h<1,256><<<gp, blk, SM256>>>(att, woh, x1, x, MTOK, DM, DM,
                                      DM, DM, DM, 1.f, 1, 0, 0, 0, 0, 0, 0, 0);

    // LN2
    ln_kernel<<<MTOK, blk>>>(x1, l2w, l2b, ln);

    // gate = ln @ wg^T (fp32 out)
    dim3 gf(FF / 256, MTOK / 128, 1);
    gemm_h<0,256><<<gf, blk, SM256>>>(ln, wgh, gate, nullptr, MTOK, FF, DM,
                                      DM, DM, FF, 1.f, 1, 0, 0, 0, 0, 0, 0, 0);

    // hid = silu(gate) * (ln @ wu^T) (fp16 out)
    gemm_h<2,256><<<gf, blk, SM256>>>(ln, wuh, hid, gate, MTOK, FF, DM,
                                      DM, DM, FF, 1.f, 1, 0, 0, 0, 0, 0, 0, 0);

    // out = x1 + hid @ wd^T
    dim3 gd(DM / 256, MTOK / 128, 1);
    gemm_h<1,256><<<gd, blk, SM256>>>(hid, wdh, out, x1, MTOK, DM, FF,
                                      FF, FF, DM, 1.f, 1, 0, 0, 0, 0, 0, 0, 0);
}